// round 5
// baseline (speedup 1.0000x reference)
#include <cuda_runtime.h>
#include <math_constants.h>

#define Bb 4
#define Cc 64
#define C2c 32
#define Nn 1024
#define Vv 20
#define Pp (Bb*Nn*Vv)          // 81920 points
#define NVv (Nn*Vv)            // 20480
#define BNb (Bb*Nn)            // 4096 tiles
#define OUTSZ (Bb*Cc*Nn*Vv)    // 5242880
#define EPSc 1e-5f

// -------- scratch (device globals; no allocation allowed) --------
__device__ float g_xm[C2c*Pp];        // masked embed pre-BN, layout [c2][p]
__device__ float g_u[OUTSZ];          // u, layout (b,o,n,v) == output layout
__device__ float g_T[Bb*Cc*Nn];       // max_v t, layout [b][o][n]
__device__ float g_est[64];           // embed: sum[0:32], sumsq[32:64]
__device__ float g_cst[320];          // conv: S1,S2,S3,S4,Cx each [64]

// -------- f32x2 helpers --------
__device__ __forceinline__ unsigned long long dup2(float x) {
    unsigned long long r;
    asm("mov.b64 %0, {%1, %1};" : "=l"(r) : "f"(x));
    return r;
}
__device__ __forceinline__ void fma2(unsigned long long& d, unsigned long long a, unsigned long long b) {
    asm("fma.rn.f32x2 %0, %1, %2, %0;" : "+l"(d) : "l"(a), "l"(b));
}
__device__ __forceinline__ float2 unpk2(unsigned long long v) {
    float2 r;
    asm("mov.b64 {%0, %1}, %2;" : "=f"(r.x), "=f"(r.y) : "l"(v));
    return r;
}

// ==================== K0: zero accumulators ====================
__global__ void k0_zero() {
    int t = threadIdx.x;
    if (t < 64) g_est[t] = 0.f;
    else if (t < 384) g_cst[t - 64] = 0.f;
}

// ==================== K1: embed GEMM + masked stats ====================
// 2 consecutive points per thread. xm = mask * (feats . wE^T + bE)
__global__ void __launch_bounds__(128) k1_embed(
    const float* __restrict__ feats, const float* __restrict__ mask,
    const float* __restrict__ wE, const float* __restrict__ bE)
{
    __shared__ __align__(16) float wsh[Cc*C2c];  // [c][o]; o pairs adjacent
    __shared__ float sacc[64];                   // block stats
    int tid = threadIdx.x;
    for (int j = tid; j < Cc*C2c; j += 128) {
        int o = j >> 6, c = j & 63;
        wsh[c*C2c + o] = wE[j];
    }
    if (tid < 64) sacc[tid] = 0.f;
    __syncthreads();

    int t  = blockIdx.x * 128 + tid;         // 320*128 = 40960 thread-pairs
    int p0 = 2 * t;
    int b  = p0 / NVv;
    int nv = p0 - b * NVv;
    const float* fptr = feats + (size_t)b * Cc * NVv + nv;
    const ulonglong2* wsh4 = (const ulonglong2*)wsh;   // 8 per c

    unsigned long long accA[16], accB[16];
    #pragma unroll
    for (int j = 0; j < 16; ++j) { accA[j] = 0ULL; accB[j] = 0ULL; }

    #pragma unroll 4
    for (int c = 0; c < Cc; ++c) {
        float2 f = *(const float2*)(fptr + c * NVv);
        unsigned long long fa = dup2(f.x), fb = dup2(f.y);
        #pragma unroll
        for (int j = 0; j < 8; ++j) {
            ulonglong2 w = wsh4[c*8 + j];
            fma2(accA[2*j],   w.x, fa);
            fma2(accB[2*j],   w.x, fb);
            fma2(accA[2*j+1], w.y, fa);
            fma2(accB[2*j+1], w.y, fb);
        }
    }

    float m0 = __ldg(mask + p0), m1 = __ldg(mask + p0 + 1);
    int lane = tid & 31;

    #pragma unroll
    for (int j = 0; j < 16; ++j) {
        float2 va = unpk2(accA[j]);      // point p0: (o0, o1)
        float2 vb = unpk2(accB[j]);      // point p0+1
        int o0 = 2*j, o1 = 2*j + 1;
        float b0 = __ldg(bE + o0), b1 = __ldg(bE + o1);
        float x00 = (va.x + b0) * m0;
        float x01 = (vb.x + b0) * m1;
        float x10 = (va.y + b1) * m0;
        float x11 = (vb.y + b1) * m1;
        *(float2*)(g_xm + (size_t)o0*Pp + p0) = make_float2(x00, x01);
        *(float2*)(g_xm + (size_t)o1*Pp + p0) = make_float2(x10, x11);
        // partial butterfly to 8-lane granularity (3 steps), 4 lanes atomic
        float s0 = x00 + x01, q0 = x00*x00 + x01*x01;
        float s1 = x10 + x11, q1 = x10*x10 + x11*x11;
        #pragma unroll
        for (int d = 1; d <= 4; d <<= 1) {
            s0 += __shfl_xor_sync(0xffffffffu, s0, d);
            q0 += __shfl_xor_sync(0xffffffffu, q0, d);
            s1 += __shfl_xor_sync(0xffffffffu, s1, d);
            q1 += __shfl_xor_sync(0xffffffffu, q1, d);
        }
        if ((lane & 7) == 0) {
            atomicAdd(&sacc[o0], s0);      atomicAdd(&sacc[32 + o0], q0);
            atomicAdd(&sacc[o1], s1);      atomicAdd(&sacc[32 + o1], q1);
        }
    }
    __syncthreads();
    if (tid < 64) atomicAdd(&g_est[tid], sacc[tid]);
}

// ==================== K3: u/t GEMV + conv stats + T ====================
// 1024 blocks x 128 threads. Each block: 4 tiles, 2 concurrent (64 thr each).
// Thread (half, o): computes BOTH u-row (W1-W2) and t-row (W2) for its o,
// sharing the x-tile LDS.128 reads between them. Embed-BN finalized inline.
__global__ void __launch_bounds__(128) k3_conv(
    const float* __restrict__ mask, const float* __restrict__ wC,
    const float* __restrict__ gE, const float* __restrict__ beE)
{
    __shared__ float wsh[64*65];                       // padded weight rows
    __shared__ __align__(16) float xs[2][C2c*Vv];      // per-half x tile
    __shared__ float bnA[64];                          // scale[0:32] shift[32:64]

    int tid  = threadIdx.x;
    int half = tid >> 6;
    int o    = tid & 63;

    for (int j = tid; j < 64*64; j += 128)
        wsh[(j >> 6) * 65 + (j & 63)] = wC[j];

    if (tid < 32) {                                    // finalize embed BN
        float inv  = 1.f / (float)Pp;
        float mean = g_est[tid] * inv;
        float var  = g_est[32 + tid] * inv - mean * mean;
        float sc   = rsqrtf(var + EPSc) * __ldg(gE + tid);
        bnA[tid]      = sc;
        bnA[32 + tid] = __ldg(beE + tid) - mean * sc;
    }
    __syncthreads();

    // weights to registers (scalar)
    float wdU[32], wdT[32];
    #pragma unroll
    for (int c2 = 0; c2 < 32; ++c2) {
        float w2 = wsh[o*65 + 32 + c2];
        wdU[c2] = wsh[o*65 + c2] - w2;
        wdT[c2] = w2;
    }

    float S1 = 0.f, S2 = 0.f, S3 = 0.f, S4 = 0.f, CX = 0.f;

    #pragma unroll
    for (int it2 = 0; it2 < 2; ++it2) {
        __syncthreads();                               // previous xs reads done
        // load x tiles for both halves: 1280 values / 128 threads = 10 each
        #pragma unroll
        for (int k = 0; k < 10; ++k) {
            int i  = tid + k * 128;
            int h  = i / 640;
            int j  = i - h * 640;
            int c2 = j / Vv, v = j - c2 * Vv;
            int tId = blockIdx.x * 4 + it2 * 2 + h;
            int p  = tId * Vv + v;
            float val = g_xm[(size_t)c2 * Pp + p];
            xs[h][c2*Vv + v] =
                fmaxf(fmaf(val, bnA[c2], bnA[32 + c2]), 0.f) * __ldg(mask + p);
        }
        __syncthreads();

        int tileId = blockIdx.x * 4 + it2 * 2 + half;
        const ulonglong2* xv = (const ulonglong2*)xs[half];   // 5 per c2

        unsigned long long ua[10], ta[10];
        #pragma unroll
        for (int q = 0; q < 10; ++q) { ua[q] = 0ULL; ta[q] = 0ULL; }

        #pragma unroll
        for (int c2 = 0; c2 < 32; ++c2) {
            unsigned long long wu = dup2(wdU[c2]);
            unsigned long long wt = dup2(wdT[c2]);
            #pragma unroll
            for (int q = 0; q < 5; ++q) {
                ulonglong2 x = xv[c2*5 + q];
                fma2(ua[2*q],   wu, x.x);
                fma2(ua[2*q+1], wu, x.y);
                fma2(ta[2*q],   wt, x.x);
                fma2(ta[2*q+1], wt, x.y);
            }
        }

        float a[20], tt[20];
        #pragma unroll
        for (int q = 0; q < 10; ++q) {
            float2 v1 = unpk2(ua[q]); a[2*q] = v1.x; a[2*q+1] = v1.y;
            float2 v2 = unpk2(ta[q]); tt[2*q] = v2.x; tt[2*q+1] = v2.y;
        }

        float su = 0.f, qu = 0.f, st = 0.f, qt = 0.f, mxt = -CUDART_INF_F;
        #pragma unroll
        for (int v = 0; v < 20; ++v) {
            su += a[v];  qu += a[v]*a[v];
            st += tt[v]; qt += tt[v]*tt[v];
            mxt = fmaxf(mxt, tt[v]);
        }

        int b = tileId >> 10, n = tileId & 1023;
        float4* up = (float4*)(g_u + ((size_t)(b*Cc + o) * Nn + n) * Vv);
        #pragma unroll
        for (int k = 0; k < 5; ++k)
            up[k] = make_float4(a[4*k], a[4*k+1], a[4*k+2], a[4*k+3]);
        g_T[(b*Cc + o) * Nn + n] = mxt;

        S1 += su; S2 += qu; S3 += st; S4 += qt; CX += su * st;
    }

    atomicAdd(&g_cst[o],       S1);
    atomicAdd(&g_cst[64  + o], S2);
    atomicAdd(&g_cst[128 + o], S3);
    atomicAdd(&g_cst[192 + o], S4);
    atomicAdd(&g_cst[256 + o], CX);
}

// ==================== K5: epilogue (4x float4/thread) ====================
// out = feats + mask * relu((u + T) * scale + shift)
// Each block covers 1024 consecutive float4 of a single (b,o) (5120 per bo,
// 5 blocks/bo). bn computed per thread (uniform L2 reads, no sync).
__global__ void __launch_bounds__(256) k5_out(
    const float* __restrict__ feats, const float* __restrict__ mask,
    const float* __restrict__ gC, const float* __restrict__ beC,
    float* __restrict__ out)
{
    int base = blockIdx.x * 1024 + threadIdx.x;   // grid: 1280 blocks
    int bo   = blockIdx.x / 5;                    // 5 blocks per (b,o)
    int b    = bo >> 6, o = bo & 63;

    // conv BN finalize (per thread; all reads uniform -> L2 broadcast)
    float Sa = g_cst[o], Sb = g_cst[64+o], Sc = g_cst[128+o],
          Sd = g_cst[192+o], Cx = g_cst[256+o];
    const float invM = 1.f / ((float)Bb * Nn * Vv * Vv);
    float mean = (float)Vv * (Sa + Sc) * invM;
    float ey2  = ((float)Vv * (Sb + Sd) + 2.f * Cx) * invM;
    float sc   = rsqrtf(ey2 - mean * mean + EPSc) * __ldg(gC + o);
    float sh   = __ldg(beC + o) - mean * sc;

    float4 u4[4], f4[4], m4[4];
    float  T[4];
    #pragma unroll
    for (int k = 0; k < 4; ++k) {
        int idx4 = base + k * 256;
        int row  = idx4 / 5;                      // (b,o,n)
        int v4   = idx4 - row * 5;
        int n    = row & 1023;
        u4[k] = *((const float4*)g_u + idx4);
        f4[k] = __ldg((const float4*)feats + idx4);
        m4[k] = __ldg((const float4*)mask + (size_t)(b * Nn + n) * 5 + v4);
        T[k]  = g_T[row];
    }
    #pragma unroll
    for (int k = 0; k < 4; ++k) {
        int idx4 = base + k * 256;
        float4 r;
        r.x = f4[k].x + m4[k].x * fmaxf(fmaf(u4[k].x + T[k], sc, sh), 0.f);
        r.y = f4[k].y + m4[k].y * fmaxf(fmaf(u4[k].y + T[k], sc, sh), 0.f);
        r.z = f4[k].z + m4[k].z * fmaxf(fmaf(u4[k].z + T[k], sc, sh), 0.f);
        r.w = f4[k].w + m4[k].w * fmaxf(fmaf(u4[k].w + T[k], sc, sh), 0.f);
        ((float4*)out)[idx4] = r;
    }
}

// ==================== launch ====================
extern "C" void kernel_launch(void* const* d_in, const int* in_sizes, int n_in,
                              void* d_out, int out_size) {
    const float* feats = (const float*)d_in[0];
    const float* mask  = (const float*)d_in[1];
    const float* wE    = (const float*)d_in[2];
    const float* bE    = (const float*)d_in[3];
    const float* gE    = (const float*)d_in[4];
    const float* beE   = (const float*)d_in[5];
    const float* wC    = (const float*)d_in[6];
    const float* gC    = (const float*)d_in[7];
    const float* beC   = (const float*)d_in[8];
    float* out = (float*)d_out;

    k0_zero<<<1, 384>>>();
    k1_embed<<<320, 128>>>(feats, mask, wE, bE);
    k3_conv<<<BNb/4, 128>>>(mask, wC, gE, beE);              // 1024 blocks
    k5_out<<<OUTSZ/4096, 256>>>(feats, mask, gC, beC, out);  // 1280 blocks
}